// round 9
// baseline (speedup 1.0000x reference)
#include <cuda_runtime.h>
#include <cuda_bf16.h>
#include <cstdint>
#include <math.h>

#define NTOK 8192
#define DDIM 2048
#define HDIM 1408
#define NEXP 8
#define KBLK_D  32
#define KBLK_H  22
#define NBLK_GU 11
#define NBLK_DN 16
#define RBLKS   576
#define TILE_E  8192
#define TILE_B  16384

typedef unsigned int u32;
typedef unsigned long long u64b;

__device__ __host__ __forceinline__ u32 SWZ(u32 x) { return x ^ ((x >> 3) & 0x70); }

// ---------------- static device scratch ----------------
__device__ int   d_cnt[16];
__device__ int   d_row_token[9 * NTOK];
__device__ float d_row_w[9 * NTOK];
__device__ __align__(1024) __nv_bfloat16 d_xg_hi[(size_t)RBLKS * KBLK_D * TILE_E];
__device__ __align__(1024) __nv_bfloat16 d_xg_lo[(size_t)RBLKS * KBLK_D * TILE_E];
__device__ __align__(1024) __nv_bfloat16 d_wg_hi[(size_t)9 * NBLK_GU * KBLK_D * TILE_E];
__device__ __align__(1024) __nv_bfloat16 d_wg_lo[(size_t)9 * NBLK_GU * KBLK_D * TILE_E];
__device__ __align__(1024) __nv_bfloat16 d_wu_hi[(size_t)9 * NBLK_GU * KBLK_D * TILE_E];
__device__ __align__(1024) __nv_bfloat16 d_wu_lo[(size_t)9 * NBLK_GU * KBLK_D * TILE_E];
__device__ __align__(1024) __nv_bfloat16 d_wd_hi[(size_t)9 * NBLK_DN * KBLK_H * TILE_E];
__device__ __align__(1024) __nv_bfloat16 d_wd_lo[(size_t)9 * NBLK_DN * KBLK_H * TILE_E];
__device__ __align__(1024) __nv_bfloat16 d_act_hi[(size_t)RBLKS * KBLK_H * TILE_E];
__device__ __align__(1024) __nv_bfloat16 d_act_lo[(size_t)RBLKS * KBLK_H * TILE_E];

// ---------------- PTX helpers (baseline compute_103 only) ----------------
__device__ __forceinline__ u32 smem_u32(const void* p) {
    u32 a;
    asm("{ .reg .u64 t; cvta.to.shared.u64 t, %1; cvt.u32.u64 %0, t; }" : "=r"(a) : "l"(p));
    return a;
}
#define MBARRIER_INIT(a, c) \
    asm volatile("mbarrier.init.shared.b64 [%0], %1;" :: "r"((u32)(a)), "r"((u32)(c)) : "memory")
#define MBARRIER_EXPECT_TX(a, b) \
    asm volatile("mbarrier.arrive.expect_tx.shared.b64 _, [%0], %1;" :: "r"((u32)(a)), "r"((u32)(b)) : "memory")
#define MBAR_WAIT_ACQ(mbar, parity) do {                                         \
    u32 _m = (u32)(mbar); u32 _p = (u32)(parity); u32 _d;                        \
    asm volatile("{\n\t.reg .pred p;\n\t"                                        \
        "mbarrier.try_wait.parity.acquire.cta.shared::cta.b64 p, [%1], %2;\n\t"  \
        "selp.b32 %0, 1, 0, p;\n\t}" : "=r"(_d) : "r"(_m), "r"(_p) : "memory");  \
    if (!_d) {                                                                   \
        asm volatile("{\n\t.reg .pred P1;\n\t"                                   \
            "WL%=:\n\t"                                                          \
            "mbarrier.try_wait.parity.acquire.cta.shared::cta.b64 P1, [%0], %1, 0x989680;\n\t" \
            "@P1 bra.uni WD%=;\n\t"                                              \
            "bra.uni WL%=;\n\tWD%=:\n\t}" :: "r"(_m), "r"(_p) : "memory");       \
    }                                                                            \
} while (0)

__device__ __forceinline__ void bulk_g2s(u32 dst, const void* src, u32 bytes, u32 mbar) {
    asm volatile("cp.async.bulk.shared::cluster.global.mbarrier::complete_tx::bytes [%0], [%1], %2, [%3];"
        :: "r"(dst), "l"(src), "r"(bytes), "r"(mbar) : "memory");
}

__device__ __forceinline__ void ldsm4(u32& r0, u32& r1, u32& r2, u32& r3, u32 addr) {
    asm volatile("ldmatrix.sync.aligned.m8n8.x4.shared.b16 {%0,%1,%2,%3}, [%4];"
        : "=r"(r0), "=r"(r1), "=r"(r2), "=r"(r3) : "r"(addr));
}
__device__ __forceinline__ void mma16816(float* c, const u32* a, u32 b0, u32 b1) {
    asm volatile("mma.sync.aligned.m16n8k16.row.col.f32.bf16.bf16.f32 "
        "{%0,%1,%2,%3}, {%4,%5,%6,%7}, {%8,%9}, {%0,%1,%2,%3};"
        : "+f"(c[0]), "+f"(c[1]), "+f"(c[2]), "+f"(c[3])
        : "r"(a[0]), "r"(a[1]), "r"(a[2]), "r"(a[3]), "r"(b0), "r"(b1));
}

__device__ __forceinline__ u32 split_pair(float v0, float v1, u32& lo_out) {
    __nv_bfloat16 h0 = __float2bfloat16_rn(v0);
    __nv_bfloat16 h1 = __float2bfloat16_rn(v1);
    __nv_bfloat16 l0 = __float2bfloat16_rn(v0 - __bfloat162float(h0));
    __nv_bfloat16 l1 = __float2bfloat16_rn(v1 - __bfloat162float(h1));
    lo_out = ((u32)__bfloat16_as_ushort(l1) << 16) | (u32)__bfloat16_as_ushort(l0);
    return ((u32)__bfloat16_as_ushort(h1) << 16) | (u32)__bfloat16_as_ushort(h0);
}
__device__ __forceinline__ float silu_f(float g) { return g / (1.f + expf(-g)); }

// ---------------- init + router ----------------
__global__ void init_kernel() { if (threadIdx.x < 16) d_cnt[threadIdx.x] = 0; }

__global__ void router_kernel(const float* __restrict__ x, const float* __restrict__ Wr,
                              const float* __restrict__ br, const float* __restrict__ rb) {
    int g = blockIdx.x * blockDim.x + threadIdx.x;
    int t = g >> 5, lane = g & 31;
    if (t >= NTOK) return;
    const float* xr = x + (size_t)t * DDIM;
    float acc[NEXP];
#pragma unroll
    for (int e = 0; e < NEXP; e++) acc[e] = 0.f;
    for (int d = lane; d < DDIM; d += 32) {
        float xv = xr[d];
        const float* wr = Wr + d * NEXP;
#pragma unroll
        for (int e = 0; e < NEXP; e++) acc[e] += xv * wr[e];
    }
#pragma unroll
    for (int off = 16; off > 0; off >>= 1)
#pragma unroll
        for (int e = 0; e < NEXP; e++) acc[e] += __shfl_xor_sync(0xffffffffu, acc[e], off);
    if (lane == 0) {
        float p[NEXP];
#pragma unroll
        for (int e = 0; e < NEXP; e++) p[e] = 1.f / (1.f + expf(-(acc[e] + br[e] + rb[e])));
        int i0 = 0;
#pragma unroll
        for (int e = 1; e < NEXP; e++) if (p[e] > p[i0]) i0 = e;
        int i1 = (i0 == 0) ? 1 : 0;
#pragma unroll
        for (int e = 0; e < NEXP; e++) if (e != i0 && p[e] > p[i1]) i1 = e;
        float s = p[i0] + p[i1];
        int r0 = atomicAdd(&d_cnt[i0], 1);
        d_row_token[i0 * NTOK + r0] = t;
        d_row_w[i0 * NTOK + r0] = p[i0] / s;
        int r1 = atomicAdd(&d_cnt[i1], 1);
        d_row_token[i1 * NTOK + r1] = t;
        d_row_w[i1 * NTOK + r1] = p[i1] / s;
        d_row_token[NEXP * NTOK + t] = t;
        d_row_w[NEXP * NTOK + t] = 1.f;
    }
}

// ---------------- merged weight convert (gate/up/down in one launch) --------
__global__ void conv_w_all(const float* __restrict__ Wg, const float* __restrict__ Wg_s,
                           const float* __restrict__ Wu, const float* __restrict__ Wu_s,
                           const float* __restrict__ Wd, const float* __restrict__ Wd_s) {
    int kb = blockIdx.x, nb = blockIdx.y;
    int sel = blockIdx.z / 9, e = blockIdx.z % 9;
    int Kdim = (sel == 2) ? HDIM : DDIM;
    int Ndim = (sel == 2) ? DDIM : HDIM;
    int kblk = (sel == 2) ? KBLK_H : KBLK_D;
    int nblk = (sel == 2) ? NBLK_DN : NBLK_GU;
    if (kb >= kblk || nb >= nblk) return;
    const float* stk = (sel == 0) ? Wg : (sel == 1) ? Wu : Wd;
    const float* sh  = (sel == 0) ? Wg_s : (sel == 1) ? Wu_s : Wd_s;
    const float* src = (e == NEXP) ? sh : (stk + (size_t)e * Kdim * Ndim);
    __shared__ float s[64][129];
    int n0 = nb * 128, k0 = kb * 64;
    for (int i = threadIdx.x; i < 64 * 128; i += 256) {
        int kk = i >> 7, nn = i & 127;
        s[kk][nn] = src[(size_t)(k0 + kk) * Ndim + n0 + nn];
    }
    __syncthreads();
    size_t tb = ((size_t)(e * nblk + nb) * kblk + kb) * TILE_E;
    char* th = (char*)((sel == 0 ? d_wg_hi : sel == 1 ? d_wu_hi : d_wd_hi) + tb);
    char* tl = (char*)((sel == 0 ? d_wg_lo : sel == 1 ? d_wu_lo : d_wd_lo) + tb);
    int lane = threadIdx.x & 31, w = threadIdx.x >> 5;
    for (int nn = w; nn < 128; nn += 8) {
        u32 lo, hi = split_pair(s[2 * lane][nn], s[2 * lane + 1][nn], lo);
        u32 off = SWZ(nn * 128 + lane * 4);
        *(u32*)(th + off) = hi;
        *(u32*)(tl + off) = lo;
    }
}

// ---------------- gather x rows + split into SW128 tiles ----------------
__global__ void conv_x_kernel(const float* __restrict__ x) {
    int kb = blockIdx.x, rb = blockIdx.y;
    int e = rb >> 6, r0 = (rb & 63) * 128;
    int count = (e == NEXP) ? NTOK : d_cnt[e];
    if (r0 >= count) return;
    size_t tb = ((size_t)rb * KBLK_D + kb) * TILE_E;
    char* th = (char*)(d_xg_hi + tb);
    char* tl = (char*)(d_xg_lo + tb);
    int lane = threadIdx.x & 31, w = threadIdx.x >> 5;
    for (int rr = w; rr < 128; rr += 8) {
        if (r0 + rr >= count) continue;
        int tok = d_row_token[e * NTOK + r0 + rr];
        float2 v = *(const float2*)(x + (size_t)tok * DDIM + kb * 64 + lane * 2);
        u32 lo, hi = split_pair(v.x, v.y, lo);
        u32 off = SWZ(rr * 128 + lane * 4);
        *(u32*)(th + off) = hi;
        *(u32*)(tl + off) = lo;
    }
}

// ---------------- fused gate+up GEMM: 128M x 128N, 512 threads -------------
// Warps 0-7: G (2M x 4N of 64x32), warps 8-15: U.
#define GU_S 2
#define GU_STG 98304
__global__ __launch_bounds__(512, 1) void gu_kernel() {
    int nb = blockIdx.x, by = blockIdx.y, e = blockIdx.z;
    int count = (e == NEXP) ? NTOK : d_cnt[e];
    if (by * 128 >= count) return;

    extern __shared__ __align__(16) char dyn[];
    __shared__ __align__(8) u64b mbar[GU_S];
    u32 buf0 = (smem_u32(dyn) + 1023) & ~1023u;
    u32 mb = smem_u32(mbar);
    int tid = threadIdx.x, lane = tid & 31, wid = tid >> 5;

    if (tid == 0)
        for (int i = 0; i < GU_S; i++) MBARRIER_INIT(mb + 8 * i, 1);
    __syncthreads();

    int rb = e * 64 + by;
    size_t abase = (size_t)rb * KBLK_D * TILE_E;
    size_t wbase = (size_t)(e * NBLK_GU + nb) * KBLK_D * TILE_E;

    if (tid == 0) {
#pragma unroll
        for (int s = 0; s < GU_S; s++) {
            u32 fb = mb + 8 * s;
            MBARRIER_EXPECT_TX(fb, GU_STG);
            u32 dst = buf0 + s * GU_STG;
            size_t so = (size_t)s * TILE_E;
            bulk_g2s(dst,         d_xg_hi + abase + so, TILE_B, fb);
            bulk_g2s(dst + 16384, d_xg_lo + abase + so, TILE_B, fb);
            bulk_g2s(dst + 32768, d_wg_hi + wbase + so, TILE_B, fb);
            bulk_g2s(dst + 49152, d_wg_lo + wbase + so, TILE_B, fb);
            bulk_g2s(dst + 65536, d_wu_hi + wbase + so, TILE_B, fb);
            bulk_g2s(dst + 81920, d_wu_lo + wbase + so, TILE_B, fb);
        }
    }

    int w2 = wid & 7;
    int wm = w2 & 1, wn = w2 >> 1;          // wm: 2 x 64 rows, wn: 4 x 32 cols
    bool isG = wid < 8;
    int arow = wm * 64 + (lane & 15);
    u32 akoff = (lane >> 4) * 16;
    int nrow = wn * 32 + ((lane >> 4) << 3) + (lane & 7);
    u32 bkoff = ((lane >> 3) & 1) * 16;

    float acc[4][4][4];
#pragma unroll
    for (int i = 0; i < 4; i++)
#pragma unroll
        for (int n = 0; n < 4; n++)
#pragma unroll
            for (int q = 0; q < 4; q++) acc[i][n][q] = 0.f;

    for (int s = 0; s < KBLK_D; s++) {
        int b = s & 1, ph = (s >> 1) & 1;
        MBAR_WAIT_ACQ(mb + 8 * b, ph);
        u32 st = buf0 + b * GU_STG;
        u32 Ah = st, Al = st + 16384;
        u32 Bh = isG ? (st + 32768) : (st + 65536);
        u32 Bl = Bh + 16384;

        for (int j = 0; j < 4; j++) {
            u32 ah[4][4], al[4][4];
#pragma unroll
            for (int i = 0; i < 4; i++) {
                u32 off = SWZ((u32)(arow + i * 16) * 128 + j * 32 + akoff);
                ldsm4(ah[i][0], ah[i][1], ah[i][2], ah[i][3], Ah + off);
                ldsm4(al[i][0], al[i][1], al[i][2], al[i][3], Al + off);
            }
            u32 bh[8], bl[8];
#pragma unroll
            for (int p = 0; p < 2; p++) {
                u32 off = SWZ((u32)(nrow + p * 16) * 128 + j * 32 + bkoff);
                ldsm4(bh[4 * p], bh[4 * p + 1], bh[4 * p + 2], bh[4 * p + 3], Bh + off);
                ldsm4(bl[4 * p], bl[4 * p + 1], bl[4 * p + 2], bl[4 * p + 3], Bl + off);
            }
#pragma unroll
            for (int i = 0; i < 4; i++)
#pragma unroll
                for (int n = 0; n < 4; n++) {
                    mma16816(acc[i][n], ah[i], bh[2 * n], bh[2 * n + 1]);
                    mma16816(acc[i][n], ah[i], bl[2 * n], bl[2 * n + 1]);
                    mma16816(acc[i][n], al[i], bh[2 * n], bh[2 * n + 1]);
                }
        }
        __syncthreads();
        if (tid == 0 && s + GU_S < KBLK_D) {
            int ns = s + GU_S;
            u32 fb = mb + 8 * b;
            MBARRIER_EXPECT_TX(fb, GU_STG);
            u32 dst = buf0 + b * GU_STG;
            size_t so = (size_t)ns * TILE_E;
            bulk_g2s(dst,         d_xg_hi + abase + so, TILE_B, fb);
            bulk_g2s(dst + 16384, d_xg_lo + abase + so, TILE_B, fb);
            bulk_g2s(dst + 32768, d_wg_hi + wbase + so, TILE_B, fb);
            bulk_g2s(dst + 49152, d_wg_lo + wbase + so, TILE_B, fb);
            bulk_g2s(dst + 65536, d_wu_hi + wbase + so, TILE_B, fb);
            bulk_g2s(dst + 81920, d_wu_lo + wbase + so, TILE_B, fb);
        }
    }

    // ---- epilogue: exchange U via SMEM, act = silu(G)*U -> 2 swizzled tiles ----
    float* ex = (float*)dyn;   // 128 x 132 f32 = 67.6KB (reuses stage buffers)
    __syncthreads();
    if (!isG) {
#pragma unroll
        for (int i = 0; i < 4; i++)
#pragma unroll
            for (int n = 0; n < 4; n++) {
                int r0 = wm * 64 + i * 16 + (lane >> 2);
                int c = wn * 32 + n * 8 + 2 * (lane & 3);
                *(float2*)&ex[r0 * 132 + c] = make_float2(acc[i][n][0], acc[i][n][1]);
                *(float2*)&ex[(r0 + 8) * 132 + c] = make_float2(acc[i][n][2], acc[i][n][3]);
            }
    }
    __syncthreads();
    if (isG) {
        char* th0 = (char*)(d_act_hi + ((size_t)rb * KBLK_H + 2 * nb) * TILE_E);
        char* tl0 = (char*)(d_act_lo + ((size_t)rb * KBLK_H + 2 * nb) * TILE_E);
#pragma unroll
        for (int i = 0; i < 4; i++)
#pragma unroll
            for (int n = 0; n < 4; n++) {
                int r0 = wm * 64 + i * 16 + (lane >> 2);
                int c = wn * 32 + n * 8 + 2 * (lane & 3);
                float2 u0 = *(float2*)&ex[r0 * 132 + c];
                float2 u1 = *(float2*)&ex[(r0 + 8) * 132 + c];
                float a00 = silu_f(acc[i][n][0]) * u0.x;
                float a01 = silu_f(acc[i][n][1]) * u0.y;
                float a10 = silu_f(acc[i][n][2]) * u1.x;
                float a11 = silu_f(acc[i][n][3]) * u1.y;
                u32 lo0, hi0 = split_pair(a00, a01, lo0);
                u32 lo1, hi1 = split_pair(a10, a11, lo1);
                size_t tsel = (size_t)(c >> 6) * TILE_E;   // which of the 2 act tiles
                u32 o0 = SWZ((u32)r0 * 128 + (c & 63) * 2);
                u32 o1 = SWZ((u32)(r0 + 8) * 128 + (c & 63) * 2);
                *(u32*)(th0 + tsel * 2 + o0) = hi0; *(u32*)(tl0 + tsel * 2 + o0) = lo0;
                *(u32*)(th0 + tsel * 2 + o1) = hi1; *(u32*)(tl0 + tsel * 2 + o1) = lo1;
            }
    }
}

// ---------------- down GEMM: 128M x 128N, 512 threads, atomic scatter -------
#define DN_S 3
#define DN_STG 65536
__global__ __launch_bounds__(512, 1) void dn_kernel(float* __restrict__ out) {
    int nb = blockIdx.x, by = blockIdx.y, e = blockIdx.z;
    int count = (e == NEXP) ? NTOK : d_cnt[e];
    if (by * 128 >= count) return;

    extern __shared__ __align__(16) char dyn[];
    __shared__ __align__(8) u64b mbar[DN_S];
    __shared__ int   toks[128];
    __shared__ float ws[128];
    u32 buf0 = (smem_u32(dyn) + 1023) & ~1023u;
    u32 mb = smem_u32(mbar);
    int tid = threadIdx.x, lane = tid & 31, wid = tid >> 5;

    int rowbase = e * NTOK + by * 128;
    if (tid < 128) {
        toks[tid] = d_row_token[rowbase + tid];
        ws[tid]   = d_row_w[rowbase + tid];
    }
    if (tid == 0)
        for (int i = 0; i < DN_S; i++) MBARRIER_INIT(mb + 8 * i, 1);
    __syncthreads();

    int rb = e * 64 + by;
    size_t abase = (size_t)rb * KBLK_H * TILE_E;
    size_t wbase = (size_t)(e * NBLK_DN + nb) * KBLK_H * TILE_E;

    if (tid == 0) {
#pragma unroll
        for (int s = 0; s < DN_S; s++) {
            u32 fb = mb + 8 * s;
            MBARRIER_EXPECT_TX(fb, DN_STG);
            u32 dst = buf0 + s * DN_STG;
            size_t so = (size_t)s * TILE_E;
            bulk_g2s(dst,         d_act_hi + abase + so, TILE_B, fb);
            bulk_g2s(dst + 16384, d_act_lo + abase + so, TILE_B, fb);
            bulk_g2s(dst + 32768, d_wd_hi + wbase + so, TILE_B, fb);
            bulk_g2s(dst + 49152, d_wd_lo + wbase + so, TILE_B, fb);
        }
    }

    int wm = wid & 3, wn = wid >> 2;         // 4M x 4N warps, each 32x32
    int arow = wm * 32 + (lane & 15);
    u32 akoff = (lane >> 4) * 16;
    int nrow = wn * 32 + ((lane >> 4) << 3) + (lane & 7);
    u32 bkoff = ((lane >> 3) & 1) * 16;

    float acc[2][4][4];
#pragma unroll
    for (int i = 0; i < 2; i++)
#pragma unroll
        for (int n = 0; n < 4; n++)
#pragma unroll
            for (int q = 0; q < 4; q++) acc[i][n][q] = 0.f;

    for (int s = 0; s < KBLK_H; s++) {
        int b = s % DN_S, ph = (s / DN_S) & 1;
        MBAR_WAIT_ACQ(mb + 8 * b, ph);
        u32 st = buf0 + b * DN_STG;
        u32 Ah = st, Al = st + 16384, Bh = st + 32768, Bl = st + 49152;

        for (int j = 0; j < 4; j++) {
            u32 ah[2][4], al[2][4];
#pragma unroll
            for (int i = 0; i < 2; i++) {
                u32 off = SWZ((u32)(arow + i * 16) * 128 + j * 32 + akoff);
                ldsm4(ah[i][0], ah[i][1], ah[i][2], ah[i][3], Ah + off);
                ldsm4(al[i][0], al[i][1], al[i][2], al[i][3], Al + off);
            }
            u32 bh[8], bl[8];
#pragma unroll
            for (int p = 0; p < 2; p++) {
                u32 off = SWZ((u32)(nrow + p * 16) * 128 + j * 32 + bkoff);
                ldsm4(bh[4 * p], bh[4 * p + 1], bh[4 * p + 2], bh[4 * p + 3], Bh + off);
                ldsm4(bl[4 * p], bl[4 * p + 1], bl[4 * p + 2], bl[4 * p + 3], Bl + off);
            }
#pragma unroll
            for (int i = 0; i < 2; i++)
#pragma unroll
                for (int n = 0; n < 4; n++) {
                    mma16816(acc[i][n], ah[i], bh[2 * n], bh[2 * n + 1]);
                    mma16816(acc[i][n], ah[i], bl[2 * n], bl[2 * n + 1]);
                    mma16816(acc[i][n], al[i], bh[2 * n], bh[2 * n + 1]);
                }
        }
        __syncthreads();
        if (tid == 0 && s + DN_S < KBLK_H) {
            int ns = s + DN_S;
            u32 fb = mb + 8 * b;
            MBARRIER_EXPECT_TX(fb, DN_STG);
            u32 dst = buf0 + b * DN_STG;
            size_t so = (size_t)ns * TILE_E;
            bulk_g2s(dst,         d_act_hi + abase + so, TILE_B, fb);
            bulk_g2s(dst + 16384, d_act_lo + abase + so, TILE_B, fb);
            bulk_g2s(dst + 32768, d_wd_hi + wbase + so, TILE_B, fb);
            bulk_g2s(dst + 49152, d_wd_lo + wbase + so, TILE_B, fb);
        }
    }

    // epilogue: weighted atomic scatter-add (masked to valid rows)
#pragma unroll
    for (int i = 0; i < 2; i++)
#pragma unroll
        for (int n = 0; n < 4; n++) {
            int r0 = wm * 32 + i * 16 + (lane >> 2);
            int c = nb * 128 + wn * 32 + n * 8 + 2 * (lane & 3);
            if (by * 128 + r0 < count) {
                float w = ws[r0];
                float* o = out + (size_t)toks[r0] * DDIM + c;
                atomicAdd(o,     w * acc[i][n][0]);
                atomicAdd(o + 1, w * acc[i][n][1]);
            }
            if (by * 128 + r0 + 8 < count) {
                float w = ws[r0 + 8];
                float* o = out + (size_t)toks[r0 + 8] * DDIM + c;
                atomicAdd(o,     w * acc[i][n][2]);
                atomicAdd(o + 1, w * acc[i][n][3]);
            }
        }
}

// ---------------- launch ----------------
extern "C" void kernel_launch(void* const* d_in, const int* in_sizes, int n_in,
                              void* d_out, int out_size) {
    const float* x    = (const float*)d_in[0];
    const float* Wg_s = (const float*)d_in[1];
    const float* Wu_s = (const float*)d_in[2];
    const float* Wd_s = (const float*)d_in[3];
    const float* Wg   = (const float*)d_in[4];
    const float* Wu   = (const float*)d_in[5];
    const float* Wd   = (const float*)d_in[6];
    const float* Wr   = (const float*)d_in[7];
    const float* br   = (const float*)d_in[8];
    const float* rb   = (const float*)d_in[9];
    (void)in_sizes; (void)n_in;

    const int GU_SMEM = 1024 + GU_S * GU_STG;   // 197632
    const int DN_SMEM = 1024 + DN_S * DN_STG;   // 197632
    cudaFuncSetAttribute(gu_kernel, cudaFuncAttributeMaxDynamicSharedMemorySize, GU_SMEM);
    cudaFuncSetAttribute(dn_kernel, cudaFuncAttributeMaxDynamicSharedMemorySize, DN_SMEM);

    cudaMemsetAsync(d_out, 0, (size_t)out_size * sizeof(float), 0);
    init_kernel<<<1, 32>>>();
    conv_w_all<<<dim3(32, 16, 27), 256>>>(Wg, Wg_s, Wu, Wu_s, Wd, Wd_s);
    router_kernel<<<(NTOK * 32 + 255) / 256, 256>>>(x, Wr, br, rb);
    conv_x_kernel<<<dim3(KBLK_D, RBLKS), 256>>>(x);

    gu_kernel<<<dim3(NBLK_GU, 64, 9), 512, GU_SMEM>>>();
    dn_kernel<<<dim3(NBLK_DN, 64, 9), 512, DN_SMEM>>>((float*)d_out);
}

// round 10
// speedup vs baseline: 1.3612x; 1.3612x over previous
#include <cuda_runtime.h>
#include <cuda_fp16.h>
#include <cstdint>
#include <math.h>

#define NTOK 8192
#define DDIM 2048
#define HDIM 1408
#define NEXP 8
#define KBLK_D  32
#define KBLK_H  22
#define NBLK_GU 11
#define NBLK_DN 16
#define RBLKS   576
#define TILE_E  8192
#define TILE_B  16384

typedef unsigned int u32;
typedef unsigned long long u64b;

__device__ __host__ __forceinline__ u32 SWZ(u32 x) { return x ^ ((x >> 3) & 0x70); }

// ---------------- static device scratch ----------------
__device__ int   d_cnt[16];
__device__ int   d_row_token[9 * NTOK];
__device__ int   d_tok_idx[2 * NTOK];
__device__ float d_tok_wt[2 * NTOK];
__device__ __align__(1024) __half d_x_hi[(size_t)RBLKS * KBLK_D * TILE_E];
__device__ __align__(1024) __half d_x_lo[(size_t)RBLKS * KBLK_D * TILE_E];
__device__ __align__(1024) __half d_wg_h[(size_t)9 * NBLK_GU * KBLK_D * TILE_E];
__device__ __align__(1024) __half d_wu_h[(size_t)9 * NBLK_GU * KBLK_D * TILE_E];
__device__ __align__(1024) __half d_wd_h[(size_t)9 * NBLK_DN * KBLK_H * TILE_E];
__device__ __align__(1024) __half d_act_hi[(size_t)RBLKS * KBLK_H * TILE_E];
__device__ __align__(1024) __half d_act_lo[(size_t)RBLKS * KBLK_H * TILE_E];
__device__ __align__(1024) float d_y[(size_t)9 * NTOK * DDIM];

// ---------------- PTX helpers (baseline compute_103 only) ----------------
__device__ __forceinline__ u32 smem_u32(const void* p) {
    u32 a;
    asm("{ .reg .u64 t; cvta.to.shared.u64 t, %1; cvt.u32.u64 %0, t; }" : "=r"(a) : "l"(p));
    return a;
}
#define MBARRIER_INIT(a, c) \
    asm volatile("mbarrier.init.shared.b64 [%0], %1;" :: "r"((u32)(a)), "r"((u32)(c)) : "memory")
#define MBARRIER_EXPECT_TX(a, b) \
    asm volatile("mbarrier.arrive.expect_tx.shared.b64 _, [%0], %1;" :: "r"((u32)(a)), "r"((u32)(b)) : "memory")
#define MBAR_WAIT_ACQ(mbar, parity) do {                                         \
    u32 _m = (u32)(mbar); u32 _p = (u32)(parity); u32 _d;                        \
    asm volatile("{\n\t.reg .pred p;\n\t"                                        \
        "mbarrier.try_wait.parity.acquire.cta.shared::cta.b64 p, [%1], %2;\n\t"  \
        "selp.b32 %0, 1, 0, p;\n\t}" : "=r"(_d) : "r"(_m), "r"(_p) : "memory");  \
    if (!_d) {                                                                   \
        asm volatile("{\n\t.reg .pred P1;\n\t"                                   \
            "WL%=:\n\t"                                                          \
            "mbarrier.try_wait.parity.acquire.cta.shared::cta.b64 P1, [%0], %1, 0x989680;\n\t" \
            "@P1 bra.uni WD%=;\n\t"                                              \
            "bra.uni WL%=;\n\tWD%=:\n\t}" :: "r"(_m), "r"(_p) : "memory");       \
    }                                                                            \
} while (0)

__device__ __forceinline__ void bulk_g2s(u32 dst, const void* src, u32 bytes, u32 mbar) {
    asm volatile("cp.async.bulk.shared::cluster.global.mbarrier::complete_tx::bytes [%0], [%1], %2, [%3];"
        :: "r"(dst), "l"(src), "r"(bytes), "r"(mbar) : "memory");
}

__device__ __forceinline__ void ldsm4(u32& r0, u32& r1, u32& r2, u32& r3, u32 addr) {
    asm volatile("ldmatrix.sync.aligned.m8n8.x4.shared.b16 {%0,%1,%2,%3}, [%4];"
        : "=r"(r0), "=r"(r1), "=r"(r2), "=r"(r3) : "r"(addr));
}
__device__ __forceinline__ void mma16816(float* c, const u32* a, u32 b0, u32 b1) {
    asm volatile("mma.sync.aligned.m16n8k16.row.col.f32.f16.f16.f32 "
        "{%0,%1,%2,%3}, {%4,%5,%6,%7}, {%8,%9}, {%0,%1,%2,%3};"
        : "+f"(c[0]), "+f"(c[1]), "+f"(c[2]), "+f"(c[3])
        : "r"(a[0]), "r"(a[1]), "r"(a[2]), "r"(a[3]), "r"(b0), "r"(b1));
}

__device__ __forceinline__ u32 hpack(__half a, __half b) {
    return ((u32)__half_as_ushort(b) << 16) | (u32)__half_as_ushort(a);
}
__device__ __forceinline__ u32 split_pair_h(float v0, float v1, u32& lo_out) {
    __half h0 = __float2half_rn(v0), h1 = __float2half_rn(v1);
    __half l0 = __float2half_rn(v0 - __half2float(h0));
    __half l1 = __float2half_rn(v1 - __half2float(h1));
    lo_out = hpack(l0, l1);
    return hpack(h0, h1);
}
__device__ __forceinline__ u32 quant_pair_h(float v0, float v1) {
    return hpack(__float2half_rn(v0), __float2half_rn(v1));
}
__device__ __forceinline__ float silu_f(float g) { return g / (1.f + expf(-g)); }

// ---------------- init + router ----------------
__global__ void init_kernel() { if (threadIdx.x < 16) d_cnt[threadIdx.x] = 0; }

__global__ void router_kernel(const float* __restrict__ x, const float* __restrict__ Wr,
                              const float* __restrict__ br, const float* __restrict__ rb) {
    int g = blockIdx.x * blockDim.x + threadIdx.x;
    int t = g >> 5, lane = g & 31;
    if (t >= NTOK) return;
    const float* xr = x + (size_t)t * DDIM;
    float acc[NEXP];
#pragma unroll
    for (int e = 0; e < NEXP; e++) acc[e] = 0.f;
    for (int d = lane; d < DDIM; d += 32) {
        float xv = xr[d];
        const float* wr = Wr + d * NEXP;
#pragma unroll
        for (int e = 0; e < NEXP; e++) acc[e] += xv * wr[e];
    }
#pragma unroll
    for (int off = 16; off > 0; off >>= 1)
#pragma unroll
        for (int e = 0; e < NEXP; e++) acc[e] += __shfl_xor_sync(0xffffffffu, acc[e], off);
    if (lane == 0) {
        float p[NEXP];
#pragma unroll
        for (int e = 0; e < NEXP; e++) p[e] = 1.f / (1.f + expf(-(acc[e] + br[e] + rb[e])));
        int i0 = 0;
#pragma unroll
        for (int e = 1; e < NEXP; e++) if (p[e] > p[i0]) i0 = e;
        int i1 = (i0 == 0) ? 1 : 0;
#pragma unroll
        for (int e = 0; e < NEXP; e++) if (e != i0 && p[e] > p[i1]) i1 = e;
        float s = p[i0] + p[i1];
        int r0 = atomicAdd(&d_cnt[i0], 1);
        d_row_token[i0 * NTOK + r0] = t;
        int r1 = atomicAdd(&d_cnt[i1], 1);
        d_row_token[i1 * NTOK + r1] = t;
        d_row_token[NEXP * NTOK + t] = t;
        d_tok_idx[2 * t]     = i0 * NTOK + r0;
        d_tok_idx[2 * t + 1] = i1 * NTOK + r1;
        d_tok_wt[2 * t]     = p[i0] / s;
        d_tok_wt[2 * t + 1] = p[i1] / s;
    }
}

// ---------------- merged weight convert (fp16 hi only) ----------------
__global__ void conv_w_all(const float* __restrict__ Wg, const float* __restrict__ Wg_s,
                           const float* __restrict__ Wu, const float* __restrict__ Wu_s,
                           const float* __restrict__ Wd, const float* __restrict__ Wd_s) {
    int kb = blockIdx.x, nb = blockIdx.y;
    int sel = blockIdx.z / 9, e = blockIdx.z % 9;
    int Kdim = (sel == 2) ? HDIM : DDIM;
    int Ndim = (sel == 2) ? DDIM : HDIM;
    int kblk = (sel == 2) ? KBLK_H : KBLK_D;
    int nblk = (sel == 2) ? NBLK_DN : NBLK_GU;
    if (kb >= kblk || nb >= nblk) return;
    const float* stk = (sel == 0) ? Wg : (sel == 1) ? Wu : Wd;
    const float* sh  = (sel == 0) ? Wg_s : (sel == 1) ? Wu_s : Wd_s;
    const float* src = (e == NEXP) ? sh : (stk + (size_t)e * Kdim * Ndim);
    __shared__ float s[64][129];
    int n0 = nb * 128, k0 = kb * 64;
    for (int i = threadIdx.x; i < 64 * 128; i += 256) {
        int kk = i >> 7, nn = i & 127;
        s[kk][nn] = src[(size_t)(k0 + kk) * Ndim + n0 + nn];
    }
    __syncthreads();
    size_t tb = ((size_t)(e * nblk + nb) * kblk + kb) * TILE_E;
    char* th = (char*)((sel == 0 ? d_wg_h : sel == 1 ? d_wu_h : d_wd_h) + tb);
    int lane = threadIdx.x & 31, w = threadIdx.x >> 5;
    for (int nn = w; nn < 128; nn += 8) {
        u32 hi = quant_pair_h(s[2 * lane][nn], s[2 * lane + 1][nn]);
        *(u32*)(th + SWZ(nn * 128 + lane * 4)) = hi;
    }
}

// ---------------- gather x rows + split into fp16 hi/lo tiles ----------------
__global__ void conv_x_kernel(const float* __restrict__ x) {
    int kb = blockIdx.x, rb = blockIdx.y;
    int e = rb >> 6, r0 = (rb & 63) * 128;
    int count = (e == NEXP) ? NTOK : d_cnt[e];
    if (r0 >= count) return;
    size_t tb = ((size_t)rb * KBLK_D + kb) * TILE_E;
    char* th = (char*)(d_x_hi + tb);
    char* tl = (char*)(d_x_lo + tb);
    int lane = threadIdx.x & 31, w = threadIdx.x >> 5;
    for (int rr = w; rr < 128; rr += 8) {
        if (r0 + rr >= count) continue;
        int tok = d_row_token[e * NTOK + r0 + rr];
        float2 v = *(const float2*)(x + (size_t)tok * DDIM + kb * 64 + lane * 2);
        u32 lo, hi = split_pair_h(v.x, v.y, lo);
        u32 off = SWZ(rr * 128 + lane * 4);
        *(u32*)(th + off) = hi;
        *(u32*)(tl + off) = lo;
    }
}

// ---------------- fused gate+up GEMM (fp16 2-term) ----------------
// CTA: M=128, N=64 (nb of 22). Warps 0-3: G, 4-7: U; each 64x32.
#define GU_S 4
#define GU_STG 49152
__global__ __launch_bounds__(256, 1) void gu_kernel() {
    int nb = blockIdx.x, by = blockIdx.y, e = blockIdx.z;
    int count = (e == NEXP) ? NTOK : d_cnt[e];
    if (by * 128 >= count) return;

    extern __shared__ __align__(16) char dyn[];
    __shared__ __align__(8) u64b mbar[GU_S];
    u32 buf0 = (smem_u32(dyn) + 1023) & ~1023u;
    u32 mb = smem_u32(mbar);
    int tid = threadIdx.x, lane = tid & 31, wid = tid >> 5;

    if (tid == 0)
        for (int i = 0; i < GU_S; i++) MBARRIER_INIT(mb + 8 * i, 1);
    __syncthreads();

    int rb = e * 64 + by;
    size_t abase = (size_t)rb * KBLK_D * TILE_E;
    size_t wbase = (size_t)(e * NBLK_GU + (nb >> 1)) * KBLK_D * TILE_E;
    int half = (nb & 1) * 4096;  // elems (64 rows x 128B)

    if (tid == 0) {
#pragma unroll
        for (int s = 0; s < GU_S; s++) {
            u32 fb = mb + 8 * s;
            MBARRIER_EXPECT_TX(fb, GU_STG);
            u32 dst = buf0 + s * GU_STG;
            size_t so = (size_t)s * TILE_E;
            bulk_g2s(dst,         d_x_hi + abase + so, 16384, fb);
            bulk_g2s(dst + 16384, d_x_lo + abase + so, 16384, fb);
            bulk_g2s(dst + 32768, d_wg_h + wbase + so + half, 8192, fb);
            bulk_g2s(dst + 40960, d_wu_h + wbase + so + half, 8192, fb);
        }
    }

    int w2 = wid & 3;
    int wm = w2 & 1, wn = w2 >> 1;
    bool isG = wid < 4;
    int arow = wm * 64 + (lane & 15);
    u32 akoff = (lane >> 4) * 16;
    int nrow = wn * 32 + ((lane >> 4) << 3) + (lane & 7);
    u32 bkoff = ((lane >> 3) & 1) * 16;

    float acc[4][4][4];
#pragma unroll
    for (int i = 0; i < 4; i++)
#pragma unroll
        for (int n = 0; n < 4; n++)
#pragma unroll
            for (int q = 0; q < 4; q++) acc[i][n][q] = 0.f;

    for (int s = 0; s < KBLK_D; s++) {
        int b = s % GU_S, ph = (s / GU_S) & 1;
        MBAR_WAIT_ACQ(mb + 8 * b, ph);
        u32 st = buf0 + b * GU_STG;
        u32 Ah = st, Al = st + 16384;
        u32 Bh = isG ? (st + 32768) : (st + 40960);

        for (int j = 0; j < 4; j++) {
            u32 ah[4][4], al[4][4];
#pragma unroll
            for (int i = 0; i < 4; i++) {
                u32 off = SWZ((u32)(arow + i * 16) * 128 + j * 32 + akoff);
                ldsm4(ah[i][0], ah[i][1], ah[i][2], ah[i][3], Ah + off);
                ldsm4(al[i][0], al[i][1], al[i][2], al[i][3], Al + off);
            }
            u32 bh[8];
#pragma unroll
            for (int p = 0; p < 2; p++) {
                u32 off = SWZ((u32)(nrow + p * 16) * 128 + j * 32 + bkoff);
                ldsm4(bh[4 * p], bh[4 * p + 1], bh[4 * p + 2], bh[4 * p + 3], Bh + off);
            }
#pragma unroll
            for (int i = 0; i < 4; i++)
#pragma unroll
                for (int n = 0; n < 4; n++) {
                    mma16816(acc[i][n], ah[i], bh[2 * n], bh[2 * n + 1]);
                    mma16816(acc[i][n], al[i], bh[2 * n], bh[2 * n + 1]);
                }
        }
        __syncthreads();
        if (tid == 0 && s + GU_S < KBLK_D) {
            int ns = s + GU_S;
            u32 fb = mb + 8 * b;
            MBARRIER_EXPECT_TX(fb, GU_STG);
            u32 dst = buf0 + b * GU_STG;
            size_t so = (size_t)ns * TILE_E;
            bulk_g2s(dst,         d_x_hi + abase + so, 16384, fb);
            bulk_g2s(dst + 16384, d_x_lo + abase + so, 16384, fb);
            bulk_g2s(dst + 32768, d_wg_h + wbase + so + half, 8192, fb);
            bulk_g2s(dst + 40960, d_wu_h + wbase + so + half, 8192, fb);
        }
    }

    // ---- epilogue: exchange U through SMEM, act = silu(G)*U -> fp16 tiles ----
    float* ex = (float*)dyn;   // 128 x 66 f32
    __syncthreads();
    if (!isG) {
#pragma unroll
        for (int i = 0; i < 4; i++)
#pragma unroll
            for (int n = 0; n < 4; n++) {
                int r0 = wm * 64 + i * 16 + (lane >> 2);
                int c = wn * 32 + n * 8 + 2 * (lane & 3);
                *(float2*)&ex[r0 * 66 + c] = make_float2(acc[i][n][0], acc[i][n][1]);
                *(float2*)&ex[(r0 + 8) * 66 + c] = make_float2(acc[i][n][2], acc[i][n][3]);
            }
    }
    __syncthreads();
    if (isG) {
        char* th = (char*)(d_act_hi + ((size_t)rb * KBLK_H + nb) * TILE_E);
        char* tl = (char*)(d_act_lo + ((size_t)rb * KBLK_H + nb) * TILE_E);
#pragma unroll
        for (int i = 0; i < 4; i++)
#pragma unroll
            for (int n = 0; n < 4; n++) {
                int r0 = wm * 64 + i * 16 + (lane >> 2);
                int c = wn * 32 + n * 8 + 2 * (lane & 3);
                float2 u0 = *(float2*)&ex[r0 * 66 + c];
                float2 u1 = *(float2*)&ex[(r0 + 8) * 66 + c];
                float a00 = silu_f(acc[i][n][0]) * u0.x;
                float a01 = silu_f(acc[i][n][1]) * u0.y;
                float a10 = silu_f(acc[i][n][2]) * u1.x;
                float a11 = silu_f(acc[i][n][3]) * u1.y;
                u32 lo0, hi0 = split_pair_h(a00, a01, lo0);
                u32 lo1, hi1 = split_pair_h(a10, a11, lo1);
                u32 o0 = SWZ((u32)r0 * 128 + c * 2);
                u32 o1 = SWZ((u32)(r0 + 8) * 128 + c * 2);
                *(u32*)(th + o0) = hi0; *(u32*)(tl + o0) = lo0;
                *(u32*)(th + o1) = hi1; *(u32*)(tl + o1) = lo1;
            }
    }
}

// ---------------- down GEMM (fp16 2-term), writes y ----------------
// CTA: M=128, N=64 (nb of 32). 8 warps: 4(M) x 2(N), warp = 32x32.
#define DN_S 4
#define DN_STG 40960
__global__ __launch_bounds__(256, 1) void dn_kernel() {
    int nb = blockIdx.x, by = blockIdx.y, e = blockIdx.z;
    int count = (e == NEXP) ? NTOK : d_cnt[e];
    if (by * 128 >= count) return;

    extern __shared__ __align__(16) char dyn[];
    __shared__ __align__(8) u64b mbar[DN_S];
    u32 buf0 = (smem_u32(dyn) + 1023) & ~1023u;
    u32 mb = smem_u32(mbar);
    int tid = threadIdx.x, lane = tid & 31, wid = tid >> 5;

    if (tid == 0)
        for (int i = 0; i < DN_S; i++) MBARRIER_INIT(mb + 8 * i, 1);
    __syncthreads();

    int rb = e * 64 + by;
    size_t abase = (size_t)rb * KBLK_H * TILE_E;
    size_t wbase = (size_t)(e * NBLK_DN + (nb >> 1)) * KBLK_H * TILE_E;
    int half = (nb & 1) * 4096;

    if (tid == 0) {
#pragma unroll
        for (int s = 0; s < DN_S; s++) {
            u32 fb = mb + 8 * s;
            MBARRIER_EXPECT_TX(fb, DN_STG);
            u32 dst = buf0 + s * DN_STG;
            size_t so = (size_t)s * TILE_E;
            bulk_g2s(dst,         d_act_hi + abase + so, 16384, fb);
            bulk_g2s(dst + 16384, d_act_lo + abase + so, 16384, fb);
            bulk_g2s(dst + 32768, d_wd_h + wbase + so + half, 8192, fb);
        }
    }

    int wm = wid & 3, wn = wid >> 2;
    int arow = wm * 32 + (lane & 15);
    u32 akoff = (lane >> 4) * 16;
    int nrow = wn * 32 + ((lane >> 4) << 3) + (lane & 7);
    u32 bkoff = ((lane >> 3) & 1) * 16;

    float acc[2][4][4];
#pragma unroll
    for (int i = 0; i < 2; i++)
#pragma unroll
        for (int n = 0; n < 4; n++)
#pragma unroll
            for (int q = 0; q < 4; q++) acc[i][n][q] = 0.f;

    for (int s = 0; s < KBLK_H; s++) {
        int b = s % DN_S, ph = (s / DN_S) & 1;
        MBAR_WAIT_ACQ(mb + 8 * b, ph);
        u32 st = buf0 + b * DN_STG;
        u32 Ah = st, Al = st + 16384, Bh = st + 32768;

        for (int j = 0; j < 4; j++) {
            u32 ah[2][4], al[2][4];
#pragma unroll
            for (int i = 0; i < 2; i++) {
                u32 off = SWZ((u32)(arow + i * 16) * 128 + j * 32 + akoff);
                ldsm4(ah[i][0], ah[i][1], ah[i][2], ah[i][3], Ah + off);
                ldsm4(al[i][0], al[i][1], al[i][2], al[i][3], Al + off);
            }
            u32 bh[8];
#pragma unroll
            for (int p = 0; p < 2; p++) {
                u32 off = SWZ((u32)(nrow + p * 16) * 128 + j * 32 + bkoff);
                ldsm4(bh[4 * p], bh[4 * p + 1], bh[4 * p + 2], bh[4 * p + 3], Bh + off);
            }
#pragma unroll
            for (int i = 0; i < 2; i++)
#pragma unroll
                for (int n = 0; n < 4; n++) {
                    mma16816(acc[i][n], ah[i], bh[2 * n], bh[2 * n + 1]);
                    mma16816(acc[i][n], al[i], bh[2 * n], bh[2 * n + 1]);
                }
        }
        __syncthreads();
        if (tid == 0 && s + DN_S < KBLK_H) {
            int ns = s + DN_S;
            u32 fb = mb + 8 * b;
            MBARRIER_EXPECT_TX(fb, DN_STG);
            u32 dst = buf0 + b * DN_STG;
            size_t so = (size_t)ns * TILE_E;
            bulk_g2s(dst,         d_act_hi + abase + so, 16384, fb);
            bulk_g2s(dst + 16384, d_act_lo + abase + so, 16384, fb);
            bulk_g2s(dst + 32768, d_wd_h + wbase + so + half, 8192, fb);
        }
    }

    // epilogue: write raw y rows (fp32)
    float* yb = d_y + ((size_t)(e * NTOK + by * 128)) * DDIM + nb * 64;
#pragma unroll
    for (int i = 0; i < 2; i++)
#pragma unroll
        for (int n = 0; n < 4; n++) {
            int r0 = wm * 32 + i * 16 + (lane >> 2);
            int c = wn * 32 + n * 8 + 2 * (lane & 3);
            *(float2*)&yb[(size_t)r0 * DDIM + c] = make_float2(acc[i][n][0], acc[i][n][1]);
            *(float2*)&yb[(size_t)(r0 + 8) * DDIM + c] = make_float2(acc[i][n][2], acc[i][n][3]);
        }
}

// ---------------- combine: out = y_shared + w0*y0 + w1*y1 ----------------
__global__ void combine_kernel(float* __restrict__ out) {
    int t = blockIdx.x;
    int i0 = d_tok_idx[2 * t], i1 = d_tok_idx[2 * t + 1];
    float w0 = d_tok_wt[2 * t], w1 = d_tok_wt[2 * t + 1];
    const float4* ys = (const float4*)(d_y + ((size_t)(NEXP * NTOK) + t) * DDIM);
    const float4* y0 = (const float4*)(d_y + (size_t)i0 * DDIM);
    const float4* y1 = (const float4*)(d_y + (size_t)i1 * DDIM);
    float4* o = (float4*)(out + (size_t)t * DDIM);
    for (int j = threadIdx.x; j < DDIM / 4; j += blockDim.x) {
        float4 a = ys[j], b = y0[j], c = y1[j];
        float4 r;
        r.x = a.x + w0 * b.x + w1 * c.x;
        r.y = a.y + w0 * b.y + w1 * c.y;
        r.z = a.z + w0 * b.z + w1 * c.z;
        r.w = a.w + w0 * b.w + w1 * c.w;
        o[j] = r;
    }
}

// ---------------- launch ----------------
extern "C" void kernel_launch(void* const* d_in, const int* in_sizes, int n_in,
                              void* d_out, int out_size) {
    const float* x    = (const float*)d_in[0];
    const float* Wg_s = (const float*)d_in[1];
    const float* Wu_s = (const float*)d_in[2];
    const float* Wd_s = (const float*)d_in[3];
    const float* Wg   = (const float*)d_in[4];
    const float* Wu   = (const float*)d_in[5];
    const float* Wd   = (const float*)d_in[6];
    const float* Wr   = (const float*)d_in[7];
    const float* br   = (const float*)d_in[8];
    const float* rb   = (const float*)d_in[9];
    (void)in_sizes; (void)n_in; (void)out_size;

    const int GU_SMEM = 1024 + GU_S * GU_STG;   // 197632
    const int DN_SMEM = 1024 + DN_S * DN_STG;   // 164864
    cudaFuncSetAttribute(gu_kernel, cudaFuncAttributeMaxDynamicSharedMemorySize, GU_SMEM);
    cudaFuncSetAttribute(dn_kernel, cudaFuncAttributeMaxDynamicSharedMemorySize, DN_SMEM);

    init_kernel<<<1, 32>>>();
    conv_w_all<<<dim3(32, 16, 27), 256>>>(Wg, Wg_s, Wu, Wu_s, Wd, Wd_s);
    router_kernel<<<(NTOK * 32 + 255) / 256, 256>>>(x, Wr, br, rb);
    conv_x_kernel<<<dim3(KBLK_D, RBLKS), 256>>>(x);

    gu_kernel<<<dim3(22, 64, 9), 256, GU_SMEM>>>();
    dn_kernel<<<dim3(32, 64, 9), 256, DN_SMEM>>>();
    combine_kernel<<<NTOK, 256>>>((float*)d_out);
}

// round 11
// speedup vs baseline: 1.5241x; 1.1197x over previous
#include <cuda_runtime.h>
#include <cuda_fp16.h>
#include <cstdint>
#include <math.h>

#define NTOK 8192
#define DDIM 2048
#define HDIM 1408
#define NEXP 8
#define KBLK_D  32
#define KBLK_H  22
#define NBLK_GU 11
#define NBLK_DN 16
#define RBLKS   576
#define TILE_E  8192
#define TILE_B  16384

typedef unsigned int u32;
typedef unsigned long long u64b;

__device__ __host__ __forceinline__ u32 SWZ(u32 x) { return x ^ ((x >> 3) & 0x70); }

// ---------------- static device scratch ----------------
__device__ int   d_cnt[16];
__device__ int   d_row_token[9 * NTOK];
__device__ int   d_tok_idx[2 * NTOK];
__device__ float d_tok_wt[2 * NTOK];
__device__ __align__(1024) __half d_x_hi[(size_t)RBLKS * KBLK_D * TILE_E];
__device__ __align__(1024) __half d_x_lo[(size_t)RBLKS * KBLK_D * TILE_E];
__device__ __align__(1024) __half d_wg_h[(size_t)9 * NBLK_GU * KBLK_D * TILE_E];
__device__ __align__(1024) __half d_wu_h[(size_t)9 * NBLK_GU * KBLK_D * TILE_E];
__device__ __align__(1024) __half d_wd_h[(size_t)9 * NBLK_DN * KBLK_H * TILE_E];
__device__ __align__(1024) __half d_act_h[(size_t)RBLKS * KBLK_H * TILE_E];
__device__ __align__(1024) float d_y[(size_t)9 * NTOK * DDIM];

// ---------------- PTX helpers (baseline compute_103 only) ----------------
__device__ __forceinline__ u32 smem_u32(const void* p) {
    u32 a;
    asm("{ .reg .u64 t; cvta.to.shared.u64 t, %1; cvt.u32.u64 %0, t; }" : "=r"(a) : "l"(p));
    return a;
}
#define MBARRIER_INIT(a, c) \
    asm volatile("mbarrier.init.shared.b64 [%0], %1;" :: "r"((u32)(a)), "r"((u32)(c)) : "memory")
#define MBARRIER_EXPECT_TX(a, b) \
    asm volatile("mbarrier.arrive.expect_tx.shared.b64 _, [%0], %1;" :: "r"((u32)(a)), "r"((u32)(b)) : "memory")
#define MBAR_WAIT_ACQ(mbar, parity) do {                                         \
    u32 _m = (u32)(mbar); u32 _p = (u32)(parity); u32 _d;                        \
    asm volatile("{\n\t.reg .pred p;\n\t"                                        \
        "mbarrier.try_wait.parity.acquire.cta.shared::cta.b64 p, [%1], %2;\n\t"  \
        "selp.b32 %0, 1, 0, p;\n\t}" : "=r"(_d) : "r"(_m), "r"(_p) : "memory");  \
    if (!_d) {                                                                   \
        asm volatile("{\n\t.reg .pred P1;\n\t"                                   \
            "WL%=:\n\t"                                                          \
            "mbarrier.try_wait.parity.acquire.cta.shared::cta.b64 P1, [%0], %1, 0x989680;\n\t" \
            "@P1 bra.uni WD%=;\n\t"                                              \
            "bra.uni WL%=;\n\tWD%=:\n\t}" :: "r"(_m), "r"(_p) : "memory");       \
    }                                                                            \
} while (0)

__device__ __forceinline__ void bulk_g2s(u32 dst, const void* src, u32 bytes, u32 mbar) {
    asm volatile("cp.async.bulk.shared::cluster.global.mbarrier::complete_tx::bytes [%0], [%1], %2, [%3];"
        :: "r"(dst), "l"(src), "r"(bytes), "r"(mbar) : "memory");
}

__device__ __forceinline__ void ldsm4(u32& r0, u32& r1, u32& r2, u32& r3, u32 addr) {
    asm volatile("ldmatrix.sync.aligned.m8n8.x4.shared.b16 {%0,%1,%2,%3}, [%4];"
        : "=r"(r0), "=r"(r1), "=r"(r2), "=r"(r3) : "r"(addr));
}
__device__ __forceinline__ void mma16816(float* c, const u32* a, u32 b0, u32 b1) {
    asm volatile("mma.sync.aligned.m16n8k16.row.col.f32.f16.f16.f32 "
        "{%0,%1,%2,%3}, {%4,%5,%6,%7}, {%8,%9}, {%0,%1,%2,%3};"
        : "+f"(c[0]), "+f"(c[1]), "+f"(c[2]), "+f"(c[3])
        : "r"(a[0]), "r"(a[1]), "r"(a[2]), "r"(a[3]), "r"(b0), "r"(b1));
}

__device__ __forceinline__ u32 hpack(__half a, __half b) {
    return ((u32)__half_as_ushort(b) << 16) | (u32)__half_as_ushort(a);
}
__device__ __forceinline__ u32 split_pair_h(float v0, float v1, u32& lo_out) {
    __half h0 = __float2half_rn(v0), h1 = __float2half_rn(v1);
    __half l0 = __float2half_rn(v0 - __half2float(h0));
    __half l1 = __float2half_rn(v1 - __half2float(h1));
    lo_out = hpack(l0, l1);
    return hpack(h0, h1);
}
__device__ __forceinline__ u32 quant_pair_h(float v0, float v1) {
    return hpack(__float2half_rn(v0), __float2half_rn(v1));
}
__device__ __forceinline__ float silu_f(float g) { return g / (1.f + expf(-g)); }

// ---------------- init + router ----------------
__global__ void init_kernel() { if (threadIdx.x < 16) d_cnt[threadIdx.x] = 0; }

__global__ void router_kernel(const float* __restrict__ x, const float* __restrict__ Wr,
                              const float* __restrict__ br, const float* __restrict__ rb) {
    int g = blockIdx.x * blockDim.x + threadIdx.x;
    int t = g >> 5, lane = g & 31;
    if (t >= NTOK) return;
    const float* xr = x + (size_t)t * DDIM;
    float acc[NEXP];
#pragma unroll
    for (int e = 0; e < NEXP; e++) acc[e] = 0.f;
    for (int d = lane; d < DDIM; d += 32) {
        float xv = xr[d];
        const float* wr = Wr + d * NEXP;
#pragma unroll
        for (int e = 0; e < NEXP; e++) acc[e] += xv * wr[e];
    }
#pragma unroll
    for (int off = 16; off > 0; off >>= 1)
#pragma unroll
        for (int e = 0; e < NEXP; e++) acc[e] += __shfl_xor_sync(0xffffffffu, acc[e], off);
    if (lane == 0) {
        float p[NEXP];
#pragma unroll
        for (int e = 0; e < NEXP; e++) p[e] = 1.f / (1.f + expf(-(acc[e] + br[e] + rb[e])));
        int i0 = 0;
#pragma unroll
        for (int e = 1; e < NEXP; e++) if (p[e] > p[i0]) i0 = e;
        int i1 = (i0 == 0) ? 1 : 0;
#pragma unroll
        for (int e = 0; e < NEXP; e++) if (e != i0 && p[e] > p[i1]) i1 = e;
        float s = p[i0] + p[i1];
        int r0 = atomicAdd(&d_cnt[i0], 1);
        d_row_token[i0 * NTOK + r0] = t;
        int r1 = atomicAdd(&d_cnt[i1], 1);
        d_row_token[i1 * NTOK + r1] = t;
        d_row_token[NEXP * NTOK + t] = t;
        d_tok_idx[2 * t]     = i0 * NTOK + r0;
        d_tok_idx[2 * t + 1] = i1 * NTOK + r1;
        d_tok_wt[2 * t]     = p[i0] / s;
        d_tok_wt[2 * t + 1] = p[i1] / s;
    }
}

// ---------------- merged weight convert (fp16 hi only) ----------------
__global__ void conv_w_all(const float* __restrict__ Wg, const float* __restrict__ Wg_s,
                           const float* __restrict__ Wu, const float* __restrict__ Wu_s,
                           const float* __restrict__ Wd, const float* __restrict__ Wd_s) {
    int kb = blockIdx.x, nb = blockIdx.y;
    int sel = blockIdx.z / 9, e = blockIdx.z % 9;
    int Kdim = (sel == 2) ? HDIM : DDIM;
    int Ndim = (sel == 2) ? DDIM : HDIM;
    int kblk = (sel == 2) ? KBLK_H : KBLK_D;
    int nblk = (sel == 2) ? NBLK_DN : NBLK_GU;
    if (kb >= kblk || nb >= nblk) return;
    const float* stk = (sel == 0) ? Wg : (sel == 1) ? Wu : Wd;
    const float* sh  = (sel == 0) ? Wg_s : (sel == 1) ? Wu_s : Wd_s;
    const float* src = (e == NEXP) ? sh : (stk + (size_t)e * Kdim * Ndim);
    __shared__ float s[64][129];
    int n0 = nb * 128, k0 = kb * 64;
    for (int i = threadIdx.x; i < 64 * 128; i += 256) {
        int kk = i >> 7, nn = i & 127;
        s[kk][nn] = src[(size_t)(k0 + kk) * Ndim + n0 + nn];
    }
    __syncthreads();
    size_t tb = ((size_t)(e * nblk + nb) * kblk + kb) * TILE_E;
    char* th = (char*)((sel == 0 ? d_wg_h : sel == 1 ? d_wu_h : d_wd_h) + tb);
    int lane = threadIdx.x & 31, w = threadIdx.x >> 5;
    for (int nn = w; nn < 128; nn += 8) {
        u32 hi = quant_pair_h(s[2 * lane][nn], s[2 * lane + 1][nn]);
        *(u32*)(th + SWZ(nn * 128 + lane * 4)) = hi;
    }
}

// ---------------- gather x rows + split into fp16 hi/lo tiles ----------------
__global__ void conv_x_kernel(const float* __restrict__ x) {
    int kb = blockIdx.x, rb = blockIdx.y;
    int e = rb >> 6, r0 = (rb & 63) * 128;
    int count = (e == NEXP) ? NTOK : d_cnt[e];
    if (r0 >= count) return;
    size_t tb = ((size_t)rb * KBLK_D + kb) * TILE_E;
    char* th = (char*)(d_x_hi + tb);
    char* tl = (char*)(d_x_lo + tb);
    int lane = threadIdx.x & 31, w = threadIdx.x >> 5;
    for (int rr = w; rr < 128; rr += 8) {
        if (r0 + rr >= count) continue;
        int tok = d_row_token[e * NTOK + r0 + rr];
        float2 v = *(const float2*)(x + (size_t)tok * DDIM + kb * 64 + lane * 2);
        u32 lo, hi = split_pair_h(v.x, v.y, lo);
        u32 off = SWZ(rr * 128 + lane * 4);
        *(u32*)(th + off) = hi;
        *(u32*)(tl + off) = lo;
    }
}

// ---------------- fused gate+up GEMM (fp16 2-term) ----------------
// CTA: M=128, N=64 (nb of 22). Warps 0-3: G, 4-7: U; each 64x32.
#define GU_S 4
#define GU_STG 49152
__global__ __launch_bounds__(256, 1) void gu_kernel() {
    int nb = blockIdx.x, by = blockIdx.y, e = blockIdx.z;
    int count = (e == NEXP) ? NTOK : d_cnt[e];
    if (by * 128 >= count) return;

    extern __shared__ __align__(16) char dyn[];
    __shared__ __align__(8) u64b mbar[GU_S];
    u32 buf0 = (smem_u32(dyn) + 1023) & ~1023u;
    u32 mb = smem_u32(mbar);
    int tid = threadIdx.x, lane = tid & 31, wid = tid >> 5;

    if (tid == 0)
        for (int i = 0; i < GU_S; i++) MBARRIER_INIT(mb + 8 * i, 1);
    __syncthreads();

    int rb = e * 64 + by;
    size_t abase = (size_t)rb * KBLK_D * TILE_E;
    size_t wbase = (size_t)(e * NBLK_GU + (nb >> 1)) * KBLK_D * TILE_E;
    int half = (nb & 1) * 4096;  // elems (64 rows x 128B)

    if (tid == 0) {
#pragma unroll
        for (int s = 0; s < GU_S; s++) {
            u32 fb = mb + 8 * s;
            MBARRIER_EXPECT_TX(fb, GU_STG);
            u32 dst = buf0 + s * GU_STG;
            size_t so = (size_t)s * TILE_E;
            bulk_g2s(dst,         d_x_hi + abase + so, 16384, fb);
            bulk_g2s(dst + 16384, d_x_lo + abase + so, 16384, fb);
            bulk_g2s(dst + 32768, d_wg_h + wbase + so + half, 8192, fb);
            bulk_g2s(dst + 40960, d_wu_h + wbase + so + half, 8192, fb);
        }
    }

    int w2 = wid & 3;
    int wm = w2 & 1, wn = w2 >> 1;
    bool isG = wid < 4;
    int arow = wm * 64 + (lane & 15);
    u32 akoff = (lane >> 4) * 16;
    int nrow = wn * 32 + ((lane >> 4) << 3) + (lane & 7);
    u32 bkoff = ((lane >> 3) & 1) * 16;

    float acc[4][4][4];
#pragma unroll
    for (int i = 0; i < 4; i++)
#pragma unroll
        for (int n = 0; n < 4; n++)
#pragma unroll
            for (int q = 0; q < 4; q++) acc[i][n][q] = 0.f;

    for (int s = 0; s < KBLK_D; s++) {
        int b = s % GU_S, ph = (s / GU_S) & 1;
        MBAR_WAIT_ACQ(mb + 8 * b, ph);
        u32 st = buf0 + b * GU_STG;
        u32 Ah = st, Al = st + 16384;
        u32 Bh = isG ? (st + 32768) : (st + 40960);

        for (int j = 0; j < 4; j++) {
            u32 ah[4][4], al[4][4];
#pragma unroll
            for (int i = 0; i < 4; i++) {
                u32 off = SWZ((u32)(arow + i * 16) * 128 + j * 32 + akoff);
                ldsm4(ah[i][0], ah[i][1], ah[i][2], ah[i][3], Ah + off);
                ldsm4(al[i][0], al[i][1], al[i][2], al[i][3], Al + off);
            }
            u32 bh[8];
#pragma unroll
            for (int p = 0; p < 2; p++) {
                u32 off = SWZ((u32)(nrow + p * 16) * 128 + j * 32 + bkoff);
                ldsm4(bh[4 * p], bh[4 * p + 1], bh[4 * p + 2], bh[4 * p + 3], Bh + off);
            }
#pragma unroll
            for (int i = 0; i < 4; i++)
#pragma unroll
                for (int n = 0; n < 4; n++) {
                    mma16816(acc[i][n], ah[i], bh[2 * n], bh[2 * n + 1]);
                    mma16816(acc[i][n], al[i], bh[2 * n], bh[2 * n + 1]);
                }
        }
        __syncthreads();
        if (tid == 0 && s + GU_S < KBLK_D) {
            int ns = s + GU_S;
            u32 fb = mb + 8 * b;
            MBARRIER_EXPECT_TX(fb, GU_STG);
            u32 dst = buf0 + b * GU_STG;
            size_t so = (size_t)ns * TILE_E;
            bulk_g2s(dst,         d_x_hi + abase + so, 16384, fb);
            bulk_g2s(dst + 16384, d_x_lo + abase + so, 16384, fb);
            bulk_g2s(dst + 32768, d_wg_h + wbase + so + half, 8192, fb);
            bulk_g2s(dst + 40960, d_wu_h + wbase + so + half, 8192, fb);
        }
    }

    // ---- epilogue: exchange U through SMEM, act = silu(G)*U -> fp16 tile ----
    float* ex = (float*)dyn;   // 128 x 66 f32
    __syncthreads();
    if (!isG) {
#pragma unroll
        for (int i = 0; i < 4; i++)
#pragma unroll
            for (int n = 0; n < 4; n++) {
                int r0 = wm * 64 + i * 16 + (lane >> 2);
                int c = wn * 32 + n * 8 + 2 * (lane & 3);
                *(float2*)&ex[r0 * 66 + c] = make_float2(acc[i][n][0], acc[i][n][1]);
                *(float2*)&ex[(r0 + 8) * 66 + c] = make_float2(acc[i][n][2], acc[i][n][3]);
            }
    }
    __syncthreads();
    if (isG) {
        char* th = (char*)(d_act_h + ((size_t)rb * KBLK_H + nb) * TILE_E);
#pragma unroll
        for (int i = 0; i < 4; i++)
#pragma unroll
            for (int n = 0; n < 4; n++) {
                int r0 = wm * 64 + i * 16 + (lane >> 2);
                int c = wn * 32 + n * 8 + 2 * (lane & 3);
                float2 u0 = *(float2*)&ex[r0 * 66 + c];
                float2 u1 = *(float2*)&ex[(r0 + 8) * 66 + c];
                float a00 = silu_f(acc[i][n][0]) * u0.x;
                float a01 = silu_f(acc[i][n][1]) * u0.y;
                float a10 = silu_f(acc[i][n][2]) * u1.x;
                float a11 = silu_f(acc[i][n][3]) * u1.y;
                *(u32*)(th + SWZ((u32)r0 * 128 + c * 2))       = quant_pair_h(a00, a01);
                *(u32*)(th + SWZ((u32)(r0 + 8) * 128 + c * 2)) = quant_pair_h(a10, a11);
            }
    }
}

// ---------------- down GEMM (fp16 1-term), writes y ----------------
// CTA: M=128, N=64 (nb of 32). 8 warps: 4(M) x 2(N), warp = 32x32.
#define DN_S 6
#define DN_STG 24576
__global__ __launch_bounds__(256, 1) void dn_kernel() {
    int nb = blockIdx.x, by = blockIdx.y, e = blockIdx.z;
    int count = (e == NEXP) ? NTOK : d_cnt[e];
    if (by * 128 >= count) return;

    extern __shared__ __align__(16) char dyn[];
    __shared__ __align__(8) u64b mbar[DN_S];
    u32 buf0 = (smem_u32(dyn) + 1023) & ~1023u;
    u32 mb = smem_u32(mbar);
    int tid = threadIdx.x, lane = tid & 31, wid = tid >> 5;

    if (tid == 0)
        for (int i = 0; i < DN_S; i++) MBARRIER_INIT(mb + 8 * i, 1);
    __syncthreads();

    int rb = e * 64 + by;
    size_t abase = (size_t)rb * KBLK_H * TILE_E;
    size_t wbase = (size_t)(e * NBLK_DN + (nb >> 1)) * KBLK_H * TILE_E;
    int half = (nb & 1) * 4096;

    if (tid == 0) {
#pragma unroll
        for (int s = 0; s < DN_S; s++) {
            if (s >= KBLK_H) break;
            u32 fb = mb + 8 * s;
            MBARRIER_EXPECT_TX(fb, DN_STG);
            u32 dst = buf0 + s * DN_STG;
            size_t so = (size_t)s * TILE_E;
            bulk_g2s(dst,         d_act_h + abase + so, 16384, fb);
            bulk_g2s(dst + 16384, d_wd_h + wbase + so + half, 8192, fb);
        }
    }

    int wm = wid & 3, wn = wid >> 2;
    int arow = wm * 32 + (lane & 15);
    u32 akoff = (lane >> 4) * 16;
    int nrow = wn * 32 + ((lane >> 4) << 3) + (lane & 7);
    u32 bkoff = ((lane >> 3) & 1) * 16;

    float acc[2][4][4];
#pragma unroll
    for (int i = 0; i < 2; i++)
#pragma unroll
        for (int n = 0; n < 4; n++)
#pragma unroll
            for (int q = 0; q < 4; q++) acc[i][n][q] = 0.f;

    for (int s = 0; s < KBLK_H; s++) {
        int b = s % DN_S, ph = (s / DN_S) & 1;
        MBAR_WAIT_ACQ(mb + 8 * b, ph);
        u32 st = buf0 + b * DN_STG;
        u32 Ah = st, Bh = st + 16384;

        for (int j = 0; j < 4; j++) {
            u32 ah[2][4];
#pragma unroll
            for (int i = 0; i < 2; i++) {
                u32 off = SWZ((u32)(arow + i * 16) * 128 + j * 32 + akoff);
                ldsm4(ah[i][0], ah[i][1], ah[i][2], ah[i][3], Ah + off);
            }
            u32 bh[8];
#pragma unroll
            for (int p = 0; p < 2; p++) {
                u32 off = SWZ((u32)(nrow + p * 16) * 128 + j * 32 + bkoff);
                ldsm4(bh[4 * p], bh[4 * p + 1], bh[4 * p + 2], bh[4 * p + 3], Bh + off);
            }
#pragma unroll
            for (int i = 0; i < 2; i++)
#pragma unroll
                for (int n = 0; n < 4; n++)
                    mma16816(acc[i][n], ah[i], bh[2 * n], bh[2 * n + 1]);
        }
        __syncthreads();
        if (tid == 0 && s + DN_S < KBLK_H) {
            int ns = s + DN_S;
            u32 fb = mb + 8 * b;
            MBARRIER_EXPECT_TX(fb, DN_STG);
            u32 dst = buf0 + b * DN_STG;
            size_t so = (size_t)ns * TILE_E;
            bulk_g2s(dst,         d_act_h + abase + so, 16384, fb);
            bulk_g2s(dst + 16384, d_wd_h + wbase + so + half, 8192, fb);
        }
    }

    // epilogue: write raw y rows (fp32)
    float* yb = d_y + ((size_t)(e * NTOK + by * 128)) * DDIM + nb * 64;
#pragma unroll
    for (int i = 0; i < 2; i++)
#pragma unroll
        for (int n = 0; n < 4; n++) {
            int r0 = wm * 32 + i * 16 + (lane >> 2);
            int c = wn * 32 + n * 8 + 2 * (lane & 3);
            *(float2*)&yb[(size_t)r0 * DDIM + c] = make_float2(acc[i][n][0], acc[i][n][1]);
            *(float2*)&yb[(size_t)(r0 + 8) * DDIM + c] = make_float2(acc[i][n][2], acc[i][n][3]);
        }
}

// ---------------- combine: out = y_shared + w0*y0 + w1*y1 ----------------
__global__ void combine_kernel(float* __restrict__ out) {
    int t = blockIdx.x;
    int i0 = d_tok_idx[2 * t], i1 = d_tok_idx[2 * t + 1];
    float w0 = d_tok_wt[2 * t], w1 = d_tok_wt[2 * t + 1];
    const float4* ys = (const float4*)(d_y + ((size_t)(NEXP * NTOK) + t) * DDIM);
    const float4* y0 = (const float4*)(d_y + (size_t)i0 * DDIM);
    const float4* y1 = (const float4*)(d_y + (size_t)i1 * DDIM);
    float4* o = (float4*)(out + (size_t)t * DDIM);
    for (int j = threadIdx.x; j < DDIM / 4; j += blockDim.x) {
        float4 a = ys[j], b = y0[j], c = y1[j];
        float4 r;
        r.x = a.x + w0 * b.x + w1 * c.x;
        r.y = a.y + w0 * b.y + w1 * c.y;
        r.z = a.z + w0 * b.z + w1 * c.z;
        r.w = a.w + w0 * b.w + w1 * c.w;
        o[j] = r;
    }
}

// ---------------- launch ----------------
extern "C" void kernel_launch(void* const* d_in, const int* in_sizes, int n_in,
                              void* d_out, int out_size) {
    const float* x    = (const float*)d_in[0];
    const float* Wg_s = (const float*)d_in[1];
    const float* Wu_s = (const float*)d_in[2];
    const float* Wd_s = (const float*)d_in[3];
    const float* Wg   = (const float*)d_in[4];
    const float* Wu   = (const float*)d_in[5];
    const float* Wd   = (const float*)d_in[6];
    const float* Wr   = (const float*)d_in[7];
    const float* br   = (const float*)d_in[8];
    const float* rb   = (const float*)d_in[9];
    (void)in_sizes; (void)n_in; (void)out_size;

    const int GU_SMEM = 1024 + GU_S * GU_STG;   // 197632
    const int DN_SMEM = 1024 + DN_S * DN_STG;   // 148480
    cudaFuncSetAttribute(gu_kernel, cudaFuncAttributeMaxDynamicSharedMemorySize, GU_SMEM);
    cudaFuncSetAttribute(dn_kernel, cudaFuncAttributeMaxDynamicSharedMemorySize, DN_SMEM);

    init_kernel<<<1, 32>>>();
    conv_w_all<<<dim3(32, 16, 27), 256>>>(Wg, Wg_s, Wu, Wu_s, Wd, Wd_s);
    router_kernel<<<(NTOK * 32 + 255) / 256, 256>>>(x, Wr, br, rb);
    conv_x_kernel<<<dim3(KBLK_D, RBLKS), 256>>>(x);

    gu_kernel<<<dim3(22, 64, 9), 256, GU_SMEM>>>();
    dn_kernel<<<dim3(32, 64, 9), 256, DN_SMEM>>>();
    combine_kernel<<<NTOK, 256>>>((float*)d_out);
}

// round 12
// speedup vs baseline: 1.9794x; 1.2987x over previous
#include <cuda_runtime.h>
#include <cuda_fp16.h>
#include <cstdint>
#include <math.h>

#define NTOK 8192
#define DDIM 2048
#define HDIM 1408
#define NEXP 8
#define KBLK_D  32
#define KBLK_H  22
#define NBLK_GU 11
#define NBLK_DN 16
#define RBLKS   576
#define TILE_E  8192
#define TILE_B  16384

typedef unsigned int u32;
typedef unsigned long long u64b;

__device__ __host__ __forceinline__ u32 SWZ(u32 x) { return x ^ ((x >> 3) & 0x70); }

// ---------------- static device scratch ----------------
__device__ int   d_cnt[16];
__device__ int   d_row_token[9 * NTOK];
__device__ int   d_tok_idx[2 * NTOK];
__device__ float d_tok_wt[2 * NTOK];
__device__ __align__(1024) __half d_x_h[(size_t)RBLKS * KBLK_D * TILE_E];
__device__ __align__(1024) __half d_wg_h[(size_t)9 * NBLK_GU * KBLK_D * TILE_E];
__device__ __align__(1024) __half d_wu_h[(size_t)9 * NBLK_GU * KBLK_D * TILE_E];
__device__ __align__(1024) __half d_wd_h[(size_t)9 * NBLK_DN * KBLK_H * TILE_E];
__device__ __align__(1024) __half d_act_h[(size_t)RBLKS * KBLK_H * TILE_E];
__device__ __align__(1024) float d_y[(size_t)9 * NTOK * DDIM];

// ---------------- PTX helpers (baseline compute_103 only) ----------------
__device__ __forceinline__ u32 smem_u32(const void* p) {
    u32 a;
    asm("{ .reg .u64 t; cvta.to.shared.u64 t, %1; cvt.u32.u64 %0, t; }" : "=r"(a) : "l"(p));
    return a;
}
#define MBARRIER_INIT(a, c) \
    asm volatile("mbarrier.init.shared.b64 [%0], %1;" :: "r"((u32)(a)), "r"((u32)(c)) : "memory")
#define MBARRIER_EXPECT_TX(a, b) \
    asm volatile("mbarrier.arrive.expect_tx.shared.b64 _, [%0], %1;" :: "r"((u32)(a)), "r"((u32)(b)) : "memory")
#define MBAR_WAIT_ACQ(mbar, parity) do {                                         \
    u32 _m = (u32)(mbar); u32 _p = (u32)(parity); u32 _d;                        \
    asm volatile("{\n\t.reg .pred p;\n\t"                                        \
        "mbarrier.try_wait.parity.acquire.cta.shared::cta.b64 p, [%1], %2;\n\t"  \
        "selp.b32 %0, 1, 0, p;\n\t}" : "=r"(_d) : "r"(_m), "r"(_p) : "memory");  \
    if (!_d) {                                                                   \
        asm volatile("{\n\t.reg .pred P1;\n\t"                                   \
            "WL%=:\n\t"                                                          \
            "mbarrier.try_wait.parity.acquire.cta.shared::cta.b64 P1, [%0], %1, 0x989680;\n\t" \
            "@P1 bra.uni WD%=;\n\t"                                              \
            "bra.uni WL%=;\n\tWD%=:\n\t}" :: "r"(_m), "r"(_p) : "memory");       \
    }                                                                            \
} while (0)

__device__ __forceinline__ void bulk_g2s(u32 dst, const void* src, u32 bytes, u32 mbar) {
    asm volatile("cp.async.bulk.shared::cluster.global.mbarrier::complete_tx::bytes [%0], [%1], %2, [%3];"
        :: "r"(dst), "l"(src), "r"(bytes), "r"(mbar) : "memory");
}

__device__ __forceinline__ void ldsm4(u32& r0, u32& r1, u32& r2, u32& r3, u32 addr) {
    asm volatile("ldmatrix.sync.aligned.m8n8.x4.shared.b16 {%0,%1,%2,%3}, [%4];"
        : "=r"(r0), "=r"(r1), "=r"(r2), "=r"(r3) : "r"(addr));
}
__device__ __forceinline__ void mma16816(float* c, const u32* a, u32 b0, u32 b1) {
    asm volatile("mma.sync.aligned.m16n8k16.row.col.f32.f16.f16.f32 "
        "{%0,%1,%2,%3}, {%4,%5,%6,%7}, {%8,%9}, {%0,%1,%2,%3};"
        : "+f"(c[0]), "+f"(c[1]), "+f"(c[2]), "+f"(c[3])
        : "r"(a[0]), "r"(a[1]), "r"(a[2]), "r"(a[3]), "r"(b0), "r"(b1));
}

__device__ __forceinline__ u32 hpack(__half a, __half b) {
    return ((u32)__half_as_ushort(b) << 16) | (u32)__half_as_ushort(a);
}
__device__ __forceinline__ u32 quant_pair_h(float v0, float v1) {
    return hpack(__float2half_rn(v0), __float2half_rn(v1));
}
__device__ __forceinline__ float silu_f(float g) { return g / (1.f + expf(-g)); }

// ---------------- init + router ----------------
__global__ void init_kernel() { if (threadIdx.x < 16) d_cnt[threadIdx.x] = 0; }

__global__ void router_kernel(const float* __restrict__ x, const float* __restrict__ Wr,
                              const float* __restrict__ br, const float* __restrict__ rb) {
    int g = blockIdx.x * blockDim.x + threadIdx.x;
    int t = g >> 5, lane = g & 31;
    if (t >= NTOK) return;
    const float* xr = x + (size_t)t * DDIM;
    float acc[NEXP];
#pragma unroll
    for (int e = 0; e < NEXP; e++) acc[e] = 0.f;
    for (int d = lane; d < DDIM; d += 32) {
        float xv = xr[d];
        const float* wr = Wr + d * NEXP;
#pragma unroll
        for (int e = 0; e < NEXP; e++) acc[e] += xv * wr[e];
    }
#pragma unroll
    for (int off = 16; off > 0; off >>= 1)
#pragma unroll
        for (int e = 0; e < NEXP; e++) acc[e] += __shfl_xor_sync(0xffffffffu, acc[e], off);
    if (lane == 0) {
        float p[NEXP];
#pragma unroll
        for (int e = 0; e < NEXP; e++) p[e] = 1.f / (1.f + expf(-(acc[e] + br[e] + rb[e])));
        int i0 = 0;
#pragma unroll
        for (int e = 1; e < NEXP; e++) if (p[e] > p[i0]) i0 = e;
        int i1 = (i0 == 0) ? 1 : 0;
#pragma unroll
        for (int e = 0; e < NEXP; e++) if (e != i0 && p[e] > p[i1]) i1 = e;
        float s = p[i0] + p[i1];
        int r0 = atomicAdd(&d_cnt[i0], 1);
        d_row_token[i0 * NTOK + r0] = t;
        int r1 = atomicAdd(&d_cnt[i1], 1);
        d_row_token[i1 * NTOK + r1] = t;
        d_row_token[NEXP * NTOK + t] = t;
        d_tok_idx[2 * t]     = i0 * NTOK + r0;
        d_tok_idx[2 * t + 1] = i1 * NTOK + r1;
        d_tok_wt[2 * t]     = p[i0] / s;
        d_tok_wt[2 * t + 1] = p[i1] / s;
    }
}

// ---------------- merged weight convert (fp16 hi only) ----------------
__global__ void conv_w_all(const float* __restrict__ Wg, const float* __restrict__ Wg_s,
                           const float* __restrict__ Wu, const float* __restrict__ Wu_s,
                           const float* __restrict__ Wd, const float* __restrict__ Wd_s) {
    int kb = blockIdx.x, nb = blockIdx.y;
    int sel = blockIdx.z / 9, e = blockIdx.z % 9;
    int Kdim = (sel == 2) ? HDIM : DDIM;
    int Ndim = (sel == 2) ? DDIM : HDIM;
    int kblk = (sel == 2) ? KBLK_H : KBLK_D;
    int nblk = (sel == 2) ? NBLK_DN : NBLK_GU;
    if (kb >= kblk || nb >= nblk) return;
    const float* stk = (sel == 0) ? Wg : (sel == 1) ? Wu : Wd;
    const float* sh  = (sel == 0) ? Wg_s : (sel == 1) ? Wu_s : Wd_s;
    const float* src = (e == NEXP) ? sh : (stk + (size_t)e * Kdim * Ndim);
    __shared__ float s[64][129];
    int n0 = nb * 128, k0 = kb * 64;
    for (int i = threadIdx.x; i < 64 * 128; i += 256) {
        int kk = i >> 7, nn = i & 127;
        s[kk][nn] = src[(size_t)(k0 + kk) * Ndim + n0 + nn];
    }
    __syncthreads();
    size_t tb = ((size_t)(e * nblk + nb) * kblk + kb) * TILE_E;
    char* th = (char*)((sel == 0 ? d_wg_h : sel == 1 ? d_wu_h : d_wd_h) + tb);
    int lane = threadIdx.x & 31, w = threadIdx.x >> 5;
    for (int nn = w; nn < 128; nn += 8) {
        u32 hi = quant_pair_h(s[2 * lane][nn], s[2 * lane + 1][nn]);
        *(u32*)(th + SWZ(nn * 128 + lane * 4)) = hi;
    }
}

// ---------------- gather x rows into fp16 tiles ----------------
__global__ void conv_x_kernel(const float* __restrict__ x) {
    int kb = blockIdx.x, rb = blockIdx.y;
    int e = rb >> 6, r0 = (rb & 63) * 128;
    int count = (e == NEXP) ? NTOK : d_cnt[e];
    if (r0 >= count) return;
    size_t tb = ((size_t)rb * KBLK_D + kb) * TILE_E;
    char* th = (char*)(d_x_h + tb);
    int lane = threadIdx.x & 31, w = threadIdx.x >> 5;
    for (int rr = w; rr < 128; rr += 8) {
        if (r0 + rr >= count) continue;
        int tok = d_row_token[e * NTOK + r0 + rr];
        float2 v = *(const float2*)(x + (size_t)tok * DDIM + kb * 64 + lane * 2);
        *(u32*)(th + SWZ(rr * 128 + lane * 4)) = quant_pair_h(v.x, v.y);
    }
}

// ---------------- fused gate+up GEMM (fp16 1-term) ----------------
// CTA: M=128, N=64 (nb of 22). Warps 0-3: G, 4-7: U; each 64x32.
#define GU_S 6
#define GU_STG 32768
__global__ __launch_bounds__(256, 1) void gu_kernel() {
    int nb = blockIdx.x, by = blockIdx.y, e = blockIdx.z;
    int count = (e == NEXP) ? NTOK : d_cnt[e];
    if (by * 128 >= count) return;

    extern __shared__ __align__(16) char dyn[];
    __shared__ __align__(8) u64b mbar[GU_S];
    u32 buf0 = (smem_u32(dyn) + 1023) & ~1023u;
    u32 mb = smem_u32(mbar);
    int tid = threadIdx.x, lane = tid & 31, wid = tid >> 5;

    if (tid == 0)
        for (int i = 0; i < GU_S; i++) MBARRIER_INIT(mb + 8 * i, 1);
    __syncthreads();

    int rb = e * 64 + by;
    size_t abase = (size_t)rb * KBLK_D * TILE_E;
    size_t wbase = (size_t)(e * NBLK_GU + (nb >> 1)) * KBLK_D * TILE_E;
    int half = (nb & 1) * 4096;  // elems (64 rows x 128B)

    if (tid == 0) {
#pragma unroll
        for (int s = 0; s < GU_S; s++) {
            u32 fb = mb + 8 * s;
            MBARRIER_EXPECT_TX(fb, GU_STG);
            u32 dst = buf0 + s * GU_STG;
            size_t so = (size_t)s * TILE_E;
            bulk_g2s(dst,         d_x_h + abase + so, 16384, fb);
            bulk_g2s(dst + 16384, d_wg_h + wbase + so + half, 8192, fb);
            bulk_g2s(dst + 24576, d_wu_h + wbase + so + half, 8192, fb);
        }
    }

    int w2 = wid & 3;
    int wm = w2 & 1, wn = w2 >> 1;
    bool isG = wid < 4;
    int arow = wm * 64 + (lane & 15);
    u32 akoff = (lane >> 4) * 16;
    int nrow = wn * 32 + ((lane >> 4) << 3) + (lane & 7);
    u32 bkoff = ((lane >> 3) & 1) * 16;

    float acc[4][4][4];
#pragma unroll
    for (int i = 0; i < 4; i++)
#pragma unroll
        for (int n = 0; n < 4; n++)
#pragma unroll
            for (int q = 0; q < 4; q++) acc[i][n][q] = 0.f;

    for (int s = 0; s < KBLK_D; s++) {
        int b = s % GU_S, ph = (s / GU_S) & 1;
        MBAR_WAIT_ACQ(mb + 8 * b, ph);
        u32 st = buf0 + b * GU_STG;
        u32 Ah = st;
        u32 Bh = isG ? (st + 16384) : (st + 24576);

        for (int j = 0; j < 4; j++) {
            u32 ah[4][4];
#pragma unroll
            for (int i = 0; i < 4; i++) {
                u32 off = SWZ((u32)(arow + i * 16) * 128 + j * 32 + akoff);
                ldsm4(ah[i][0], ah[i][1], ah[i][2], ah[i][3], Ah + off);
            }
            u32 bh[8];
#pragma unroll
            for (int p = 0; p < 2; p++) {
                u32 off = SWZ((u32)(nrow + p * 16) * 128 + j * 32 + bkoff);
                ldsm4(bh[4 * p], bh[4 * p + 1], bh[4 * p + 2], bh[4 * p + 3], Bh + off);
            }
#pragma unroll
            for (int i = 0; i < 4; i++)
#pragma unroll
                for (int n = 0; n < 4; n++)
                    mma16816(acc[i][n], ah[i], bh[2 * n], bh[2 * n + 1]);
        }
        __syncthreads();
        if (tid == 0 && s + GU_S < KBLK_D) {
            int ns = s + GU_S;
            u32 fb = mb + 8 * b;
            MBARRIER_EXPECT_TX(fb, GU_STG);
            u32 dst = buf0 + b * GU_STG;
            size_t so = (size_t)ns * TILE_E;
            bulk_g2s(dst,         d_x_h + abase + so, 16384, fb);
            bulk_g2s(dst + 16384, d_wg_h + wbase + so + half, 8192, fb);
            bulk_g2s(dst + 24576, d_wu_h + wbase + so + half, 8192, fb);
        }
    }

    // ---- epilogue: exchange U through SMEM, act = silu(G)*U -> fp16 tile ----
    float* ex = (float*)dyn;   // 128 x 66 f32
    __syncthreads();
    if (!isG) {
#pragma unroll
        for (int i = 0; i < 4; i++)
#pragma unroll
            for (int n = 0; n < 4; n++) {
                int r0 = wm * 64 + i * 16 + (lane >> 2);
                int c = wn * 32 + n * 8 + 2 * (lane & 3);
                *(float2*)&ex[r0 * 66 + c] = make_float2(acc[i][n][0], acc[i][n][1]);
                *(float2*)&ex[(r0 + 8) * 66 + c] = make_float2(acc[i][n][2], acc[i][n][3]);
            }
    }
    __syncthreads();
    if (isG) {
        char* th = (char*)(d_act_h + ((size_t)rb * KBLK_H + nb) * TILE_E);
#pragma unroll
        for (int i = 0; i < 4; i++)
#pragma unroll
            for (int n = 0; n < 4; n++) {
                int r0 = wm * 64 + i * 16 + (lane >> 2);
                int c = wn * 32 + n * 8 + 2 * (lane & 3);
                float2 u0 = *(float2*)&ex[r0 * 66 + c];
                float2 u1 = *(float2*)&ex[(r0 + 8) * 66 + c];
                float a00 = silu_f(acc[i][n][0]) * u0.x;
                float a01 = silu_f(acc[i][n][1]) * u0.y;
                float a10 = silu_f(acc[i][n][2]) * u1.x;
                float a11 = silu_f(acc[i][n][3]) * u1.y;
                *(u32*)(th + SWZ((u32)r0 * 128 + c * 2))       = quant_pair_h(a00, a01);
                *(u32*)(th + SWZ((u32)(r0 + 8) * 128 + c * 2)) = quant_pair_h(a10, a11);
            }
    }
}

// ---------------- down GEMM (fp16 1-term), writes y ----------------
// CTA: M=128, N=64 (nb of 32). 8 warps: 4(M) x 2(N), warp = 32x32.
#define DN_S 6
#define DN_STG 24576
__global__ __launch_bounds__(256, 1) void dn_kernel() {
    int nb = blockIdx.x, by = blockIdx.y, e = blockIdx.z;
    int count = (e == NEXP) ? NTOK : d_cnt[e];
    if (by * 128 >= count) return;

    extern __shared__ __align__(16) char dyn[];
    __shared__ __align__(8) u64b mbar[DN_S];
    u32 buf0 = (smem_u32(dyn) + 1023) & ~1023u;
    u32 mb = smem_u32(mbar);
    int tid = threadIdx.x, lane = tid & 31, wid = tid >> 5;

    if (tid == 0)
        for (int i = 0; i < DN_S; i++) MBARRIER_INIT(mb + 8 * i, 1);
    __syncthreads();

    int rb = e * 64 + by;
    size_t abase = (size_t)rb * KBLK_H * TILE_E;
    size_t wbase = (size_t)(e * NBLK_DN + (nb >> 1)) * KBLK_H * TILE_E;
    int half = (nb & 1) * 4096;

    if (tid == 0) {
#pragma unroll
        for (int s = 0; s < DN_S; s++) {
            if (s >= KBLK_H) break;
            u32 fb = mb + 8 * s;
            MBARRIER_EXPECT_TX(fb, DN_STG);
            u32 dst = buf0 + s * DN_STG;
            size_t so = (size_t)s * TILE_E;
            bulk_g2s(dst,         d_act_h + abase + so, 16384, fb);
            bulk_g2s(dst + 16384, d_wd_h + wbase + so + half, 8192, fb);
        }
    }

    int wm = wid & 3, wn = wid >> 2;
    int arow = wm * 32 + (lane & 15);
    u32 akoff = (lane >> 4) * 16;
    int nrow = wn * 32 + ((lane >> 4) << 3) + (lane & 7);
    u32 bkoff = ((lane >> 3) & 1) * 16;

    float acc[2][4][4];
#pragma unroll
    for (int i = 0; i < 2; i++)
#pragma unroll
        for (int n = 0; n < 4; n++)
#pragma unroll
            for (int q = 0; q < 4; q++) acc[i][n][q] = 0.f;

    for (int s = 0; s < KBLK_H; s++) {
        int b = s % DN_S, ph = (s / DN_S) & 1;
        MBAR_WAIT_ACQ(mb + 8 * b, ph);
        u32 st = buf0 + b * DN_STG;
        u32 Ah = st, Bh = st + 16384;

        for (int j = 0; j < 4; j++) {
            u32 ah[2][4];
#pragma unroll
            for (int i = 0; i < 2; i++) {
                u32 off = SWZ((u32)(arow + i * 16) * 128 + j * 32 + akoff);
                ldsm4(ah[i][0], ah[i][1], ah[i][2], ah[i][3], Ah + off);
            }
            u32 bh[8];
#pragma unroll
            for (int p = 0; p < 2; p++) {
                u32 off = SWZ((u32)(nrow + p * 16) * 128 + j * 32 + bkoff);
                ldsm4(bh[4 * p], bh[4 * p + 1], bh[4 * p + 2], bh[4 * p + 3], Bh + off);
            }
#pragma unroll
            for (int i = 0; i < 2; i++)
#pragma unroll
                for (int n = 0; n < 4; n++)
                    mma16816(acc[i][n], ah[i], bh[2 * n], bh[2 * n + 1]);
        }
        __syncthreads();
        if (tid == 0 && s + DN_S < KBLK_H) {
            int ns = s + DN_S;
            u32 fb = mb + 8 * b;
            MBARRIER_EXPECT_TX(fb, DN_STG);
            u32 dst = buf0 + b * DN_STG;
            size_t so = (size_t)ns * TILE_E;
            bulk_g2s(dst,         d_act_h + abase + so, 16384, fb);
            bulk_g2s(dst + 16384, d_wd_h + wbase + so + half, 8192, fb);
        }
    }

    // epilogue: write raw y rows (fp32)
    float* yb = d_y + ((size_t)(e * NTOK + by * 128)) * DDIM + nb * 64;
#pragma unroll
    for (int i = 0; i < 2; i++)
#pragma unroll
        for (int n = 0; n < 4; n++) {
            int r0 = wm * 32 + i * 16 + (lane >> 2);
            int c = wn * 32 + n * 8 + 2 * (lane & 3);
            *(float2*)&yb[(size_t)r0 * DDIM + c] = make_float2(acc[i][n][0], acc[i][n][1]);
            *(float2*)&yb[(size_t)(r0 + 8) * DDIM + c] = make_float2(acc[i][n][2], acc[i][n][3]);
        }
}

// ---------------- combine: out = y_shared + w0*y0 + w1*y1 ----------------
__global__ void combine_kernel(float* __restrict__ out) {
    int t = blockIdx.x;
    int i0 = d_tok_idx[2 * t], i1 = d_tok_idx[2 * t + 1];
    float w0 = d_tok_wt[2 * t], w1 = d_tok_wt[2 * t + 1];
    const float4* ys = (const float4*)(d_y + ((size_t)(NEXP * NTOK) + t) * DDIM);
    const float4* y0 = (const float4*)(d_y + (size_t)i0 * DDIM);
    const float4* y1 = (const float4*)(d_y + (size_t)i1 * DDIM);
    float4* o = (float4*)(out + (size_t)t * DDIM);
    for (int j = threadIdx.x; j < DDIM / 4; j += blockDim.x) {
        float4 a = ys[j], b = y0[j], c = y1[j];
        float4 r;
        r.x = a.x + w0 * b.x + w1 * c.x;
        r.y = a.y + w0 * b.y + w1 * c.y;
        r.z = a.z + w0 * b.z + w1 * c.z;
        r.w = a.w + w0 * b.w + w1 * c.w;
        o[j] = r;
    }
}

// ---------------- launch ----------------
extern "C" void kernel_launch(void* const* d_in, const int* in_sizes, int n_in,
                              void* d_out, int out_size) {
    const float* x    = (const float*)d_in[0];
    const float* Wg_s = (const float*)d_in[1];
    const float* Wu_s = (const float*)d_in[2];
    const float* Wd_s = (const float*)d_in[3];
    const float* Wg   = (const float*)d_in[4];
    const float* Wu   = (const float*)d_in[5];
    const float* Wd   = (const float*)d_in[6];
    const float* Wr   = (const float*)d_in[7];
    const float* br   = (const float*)d_in[8];
    const float* rb   = (const float*)d_in[9];
    (void)in_sizes; (void)n_in; (void)out_size;

    const int GU_SMEM = 1024 + GU_S * GU_STG;   // 197632
    const int DN_SMEM = 1024 + DN_S * DN_STG;   // 148480
    cudaFuncSetAttribute(gu_kernel, cudaFuncAttributeMaxDynamicSharedMemorySize, GU_SMEM);
    cudaFuncSetAttribute(dn_kernel, cudaFuncAttributeMaxDynamicSharedMemorySize, DN_SMEM);

    init_kernel<<<1, 32>>>();
    conv_w_all<<<dim3(32, 16, 27), 256>>>(Wg, Wg_s, Wu, Wu_s, Wd, Wd_s);
    router_kernel<<<(NTOK * 32 + 255) / 256, 256>>>(x, Wr, br, rb);
    conv_x_kernel<<<dim3(KBLK_D, RBLKS), 256>>>(x);

    gu_kernel<<<dim3(22, 64, 9), 256, GU_SMEM>>>();
    dn_kernel<<<dim3(32, 64, 9), 256, DN_SMEM>>>();
    combine_kernel<<<NTOK, 256>>>((float*)d_out);
}